// round 15
// baseline (speedup 1.0000x reference)
#include <cuda_runtime.h>

#define BB 2
#define NV 12000
#define NP 32
#define CIN 5
#define CV1 64
#define CV2 128
#define GD 20
#define GC 8000
#define OC1 128
#define R1C 1210      // (10,11,11)
#define OC2 256
#define R2C 180       // (5,6,6)
#define OC3 256
#define R3C 48        // (3,4,4)

__device__ double dS1y[CV1], dQ1y[CV1];
__device__ float  fS2[CV2], fQ2[CV2];
__device__ float  gF1[BB*NV*CV1];
__device__ float  gY2[BB*NV*CV2];
__device__ int    gWin[BB*GC];
__device__ float  gSub[BB*CV2*GC];
__device__ float  gRaw1[BB*OC1*R1C];
__device__ float  gS1c[OC1], gQ1c[OC1];
__device__ float  gBg2p[8*OC2];
__device__ float  gP2[2][BB*OC2*R2C];
__device__ float  gX2bg[8*OC2];
__device__ float  gDelta2[BB*OC2*R2C];
__device__ float  gNd3p[12*OC3];
__device__ float  gP3[4][BB*OC3*R3C];
__device__ float  cwT1[CV2*27*OC1];
__device__ float  cwT2[OC1*27*OC2];
__device__ float  cwT3[OC2*27*OC3];

// ---- packed f32x2 helpers ----
__device__ __forceinline__ unsigned long long pack2(float v) {
    unsigned long long p;
    asm("mov.b64 %0, {%1, %1};" : "=l"(p) : "r"(__float_as_uint(v)));
    return p;
}
__device__ __forceinline__ unsigned long long ffma2(unsigned long long a,
                                                    unsigned long long b,
                                                    unsigned long long c) {
    unsigned long long d;
    asm("fma.rn.f32x2 %0, %1, %2, %3;" : "=l"(d) : "l"(a), "l"(b), "l"(c));
    return d;
}
__device__ __forceinline__ float2 unpack2(unsigned long long p) {
    unsigned lo, hi;
    asm("mov.b64 {%0, %1}, %2;" : "=r"(lo), "=r"(hi) : "l"(p));
    float2 r; r.x = __uint_as_float(lo); r.y = __uint_as_float(hi);
    return r;
}

// ---- cp.async helpers (4B with zero-fill predicate) ----
__device__ __forceinline__ unsigned su32(const void* p) {
    return (unsigned)__cvta_generic_to_shared(p);
}
__device__ __forceinline__ void cpa4(unsigned sa, const float* g, int ok) {
    asm volatile("cp.async.ca.shared.global [%0], [%1], 4, %2;"
                 :: "r"(sa), "l"(g), "r"(ok ? 4 : 0));
}
#define CP_COMMIT() asm volatile("cp.async.commit_group;" ::: "memory")
#define CP_WAIT1()  asm volatile("cp.async.wait_group 1;" ::: "memory")
#define CP_WAIT0()  asm volatile("cp.async.wait_group 0;" ::: "memory")

// BN1c params from conv1's atomic stats
__device__ __forceinline__ void bn1c_params(int c, const float* cb1,
                                            const float* cg1, const float* cbe1,
                                            float& sc, float& sh, float& c1) {
    float S = gS1c[c], Q = gQ1c[c];
    float bg = cb1[c];
    const float N = 81920.f, bgn = N - (float)(BB*R1C);
    float mu = (S + bg*bgn)/N;
    float var = (Q + bg*bg*bgn)/N - mu*mu;
    sc = cg1[c]*rsqrtf(var + 1e-5f);
    sh = cbe1[c] - mu*sc;
    c1 = fmaxf(bg*sc + sh, 0.f);
}

// ================= 1. init =======================================================
__global__ void k_init() {
    int i = blockIdx.x*256 + threadIdx.x;
    if (i < BB*GC) gWin[i] = -1;
    if (i < CV1) { dS1y[i] = 0.0; dQ1y[i] = 0.0; }
    if (i < CV2) { fS2[i] = 0.f; fQ2[i] = 0.f; }
    if (i < OC1) { gS1c[i] = 0.f; gQ1c[i] = 0.f; }
    if (i < 8*OC2)  gBg2p[i] = 0.f;
    if (i < 12*OC3) gNd3p[i] = 0.f;
}

// ================= 2. setupT (side stream) ======================================
__global__ void k_setupT(const float* __restrict__ cw1, const float* __restrict__ cw2,
                         const float* __restrict__ cw3) {
    int b = blockIdx.x;
    const float* src; float* dst; int J, OC;
    if (b < 432)       { src = cw1; dst = cwT1; J = 3456; OC = 128; }
    else if (b < 1296) { b -= 432;  src = cw2; dst = cwT2; J = 3456; OC = 256; }
    else               { b -= 1296; src = cw3; dst = cwT3; J = 6912; OC = 256; }
    int tO = OC/32;
    int to = b % tO, tj = b / tO;
    __shared__ float sm[32][33];
    int tx = threadIdx.x % 32, ty = threadIdx.x / 32;
    int j0 = tj*32, o0 = to*32;
    #pragma unroll
    for (int r = 0; r < 4; r++)
        sm[ty + r*8][tx] = src[(o0 + ty + r*8)*J + j0 + tx];
    __syncthreads();
    #pragma unroll
    for (int r = 0; r < 4; r++)
        dst[(j0 + ty + r*8)*OC + o0 + tx] = sm[tx][ty + r*8];
}

// ================= 3. pass1: cp.async double-buffered vf fills ==================
__global__ void k_pass1(const float* __restrict__ vf, const int* __restrict__ coords,
                        const float* __restrict__ w1, const float* __restrict__ b1) {
    __shared__ float sw[CV1*CIN], sb[CV1];
    __shared__ float sx[2][4*NP*CIN];
    __shared__ float rs[256], rq[256];
    int tid = threadIdx.x;
    int vbase = blockIdx.x*16;
    for (int i = tid; i < CV1*CIN; i += 256) sw[i] = w1[i];
    if (tid < CV1) sb[tid] = b1[tid];
    if (tid < 16) {
        int v = vbase + tid;
        int d = coords[v*3], h = coords[v*3+1], w = coords[v*3+2];
        if ((unsigned)d < GD && (unsigned)h < GD && (unsigned)w < GD)
            atomicMax(&gWin[(v/NV)*GC + (d*GD + h)*GD + w], v % NV);
    }
    for (int i = tid; i < 4*NP*CIN; i += 256)
        cpa4(su32(&sx[0][i]), vf + (size_t)vbase*NP*CIN + i, 1);
    CP_COMMIT();
    __syncthreads();
    int vloc = tid >> 6, oc = tid & 63;
    float w[CIN];
    #pragma unroll
    for (int c = 0; c < CIN; c++) w[c] = sw[oc*CIN + c];
    float bb = sb[oc];
    float sAcc = 0.f, qAcc = 0.f;
    for (int g = 0; g < 4; g++) {
        int buf = g & 1;
        if (g < 3) {
            int v1 = vbase + (g+1)*4;
            for (int i = tid; i < 4*NP*CIN; i += 256)
                cpa4(su32(&sx[buf^1][i]), vf + (size_t)v1*NP*CIN + i, 1);
            CP_COMMIT();
            CP_WAIT1();
        } else {
            CP_WAIT0();
        }
        __syncthreads();
        const float* xp = sx[buf] + vloc*NP*CIN;
        float m = -1e30f;
        #pragma unroll 4
        for (int p = 0; p < NP; p++) {
            float y = bb;
            #pragma unroll
            for (int c = 0; c < CIN; c++) y += w[c]*xp[p*CIN + c];
            m = fmaxf(m, y);
            sAcc += y; qAcc += y*y;
        }
        gF1[(vbase + g*4 + vloc)*CV1 + oc] = m;
        __syncthreads();
    }
    rs[tid] = sAcc; rq[tid] = qAcc;
    __syncthreads();
    if (tid < 64) {
        float st = rs[tid] + rs[tid+64] + rs[tid+128] + rs[tid+192];
        float qt = rq[tid] + rq[tid+64] + rq[tid+128] + rq[tid+192];
        atomicAdd(&dS1y[tid], (double)st);
        atomicAdd(&dQ1y[tid], (double)qt);
    }
}

// ================= 4. vfe2: 96 voxels/block, w2 loaded once, cp.async ===========
#define VPB 96
__global__ void k_vfe2(const float* __restrict__ w2, const float* __restrict__ b2,
                       const float* __restrict__ g1, const float* __restrict__ be1) {
    __shared__ float sf[CV1*34];
    __shared__ float sw2s[CV1*129];
    __shared__ float sc1s[CV1], sh1s[CV1];
    int tid = threadIdx.x;
    int vb0 = blockIdx.x*VPB;
    if (tid < CV1) {
        double N = (double)BB*NV*NP;
        double mu = dS1y[tid]/N, var = dQ1y[tid]/N - mu*mu;
        double sc = (double)g1[tid]*rsqrt(var + 1e-5);
        sc1s[tid] = (float)sc;
        sh1s[tid] = (float)((double)be1[tid] - mu*sc);
    }
    for (int i = tid; i < CV2*CV1; i += 128)
        cpa4(su32(&sw2s[(i & 63)*129 + (i >> 6)]), w2 + i, 1);
    for (int i = tid; i < 32*CV1; i += 128)
        cpa4(su32(&sf[(i & 63)*34 + (i >> 6)]), &gF1[(size_t)(vb0 + (i >> 6))*CV1 + (i & 63)], 1);
    CP_COMMIT();
    float bb2 = b2[tid];
    float s = 0.f, q = 0.f;
    for (int g = 0; g < 3; g++) {
        int vb = vb0 + g*32;
        CP_WAIT0();
        __syncthreads();
        for (int i = tid; i < 32*CV1; i += 128) {
            int c = i & 63, v = i >> 6;
            float f = sf[c*34 + v];
            sf[c*34 + v] = fmaxf(f*sc1s[c] + sh1s[c], 0.f);
        }
        __syncthreads();
        unsigned long long acc[16] = {};
        #pragma unroll 4
        for (int c = 0; c < CV1; c++) {
            unsigned long long w2p = pack2(sw2s[c*129 + tid]);
            const unsigned long long* fp = (const unsigned long long*)&sf[c*34];
            #pragma unroll
            for (int p = 0; p < 16; p++)
                acc[p] = ffma2(w2p, fp[p], acc[p]);
        }
        #pragma unroll
        for (int p = 0; p < 16; p++) {
            float2 y = unpack2(acc[p]);
            y.x += bb2; y.y += bb2;
            gY2[(size_t)(vb + 2*p    )*CV2 + tid] = y.x;
            gY2[(size_t)(vb + 2*p + 1)*CV2 + tid] = y.y;
            s += y.x + y.y; q += y.x*y.x + y.y*y.y;
        }
        __syncthreads();
        if (g < 2) {
            int vn = vb0 + (g+1)*32;
            for (int i = tid; i < 32*CV1; i += 128)
                cpa4(su32(&sf[(i & 63)*34 + (i >> 6)]),
                     &gF1[(size_t)(vn + (i >> 6))*CV1 + (i & 63)], 1);
            CP_COMMIT();
        }
    }
    atomicAdd(&fS2[tid], s); atomicAdd(&fQ2[tid], q);
}

// ================= 5. scatter ===================================================
__global__ void k_scatter(const float* __restrict__ g2, const float* __restrict__ be2) {
    __shared__ int swin[32];
    __shared__ float st[CV2*33];
    int tid = threadIdx.x;
    int c0 = blockIdx.x*32, b = blockIdx.y;
    if (tid < 32) swin[tid] = gWin[b*GC + c0 + tid];
    int ch = tid & 127;
    double N = (double)BB*NV;
    double mu = (double)fS2[ch]/N, var = (double)fQ2[ch]/N - mu*mu;
    double scd = (double)g2[ch]*rsqrt(var + 1e-5);
    float sc = (float)scd;
    float sh = (float)((double)be2[ch] - mu*scd);
    __syncthreads();
    #pragma unroll
    for (int pp = 0; pp < 16; pp++) {
        int cl = pp*2 + (tid >> 7);
        int win = swin[cl];
        float v = 0.f;
        if (win >= 0) v = fmaxf(gY2[(size_t)(b*NV + win)*CV2 + ch]*sc + sh, 0.f);
        st[ch*33 + cl] = v;
    }
    __syncthreads();
    #pragma unroll
    for (int k = 0; k < 16; k++) {
        int i = tid + k*256;
        int oc = i >> 5, cl = i & 31;
        gSub[(b*CV2 + oc)*GC + c0 + cl] = st[oc*33 + cl];
    }
}

// ================= 6. conv1: cp.async pipeline, 16 oc/block, inline stats =======
__global__ void k_conv1(const float* __restrict__ cb1) {
    __shared__ int sOff[1587];
    __shared__ float sIn[2][4*1587];
    __shared__ __align__(16) float sW[2][4*432];
    int ocg = blockIdx.x, od = blockIdx.y, b = blockIdx.z;   // ocg 0..7
    int tid = threadIdx.x;
    for (int i = tid; i < 1587; i += 128) {
        int kd = i/529, r = i%529, yy = r/23 - 1, xx = r%23 - 1;
        int z = 2*od - 1 + kd;
        sOff[i] = ((unsigned)z < GD && (unsigned)yy < GD && (unsigned)xx < GD)
                  ? (z*GD + yy)*GD + xx : -1;
    }
    __syncthreads();

    const float* gin = gSub + (size_t)b*CV2*GC;
    #define C1FILL(S, BUF) {                                                   \
        int c0 = (S)*4;                                                        \
        for (int i = tid; i < 4*1587; i += 128) {                              \
            int cib = i/1587, r = i - cib*1587;                                \
            int off = sOff[r];                                                 \
            cpa4(su32(&sIn[BUF][i]), gin + (c0+cib)*GC + (off<0?0:off), off>=0); \
        }                                                                      \
        for (int i = tid; i < 4*432; i += 128) {                               \
            int cib = i/432, r = i - cib*432;                                  \
            cpa4(su32(&sW[BUF][cib*432 + r]),                                  \
                 &cwT1[((c0+cib)*27 + (r>>4))*OC1 + ocg*16 + (r&15)], 1);      \
        }                                                                      \
        CP_COMMIT(); }

    C1FILL(0, 0);
    int oh = tid/11, ow = tid%11;
    bool act = tid < 121;
    unsigned long long acc[8] = {};
    for (int s = 0; s < 32; s++) {
        int buf = s & 1;
        if (s < 31) { C1FILL(s+1, buf^1); CP_WAIT1(); } else { CP_WAIT0(); }
        __syncthreads();
        if (act) {
            #pragma unroll
            for (int cib = 0; cib < 4; cib++) {
                const float* bp = sIn[buf] + cib*1587;
                #pragma unroll
                for (int kd = 0; kd < 3; kd++)
                #pragma unroll
                for (int kh = 0; kh < 3; kh++)
                #pragma unroll
                for (int kw = 0; kw < 3; kw++) {
                    float iv = bp[kd*529 + (2*oh + kh)*23 + 2*ow + kw];
                    unsigned long long pv = pack2(iv);
                    const ulonglong2* wp =
                        (const ulonglong2*)&sW[buf][(cib*27 + kd*9 + kh*3 + kw)*16];
                    ulonglong2 wa = wp[0], wb = wp[1], wc = wp[2], wd = wp[3];
                    acc[0] = ffma2(pv, wa.x, acc[0]);
                    acc[1] = ffma2(pv, wa.y, acc[1]);
                    acc[2] = ffma2(pv, wb.x, acc[2]);
                    acc[3] = ffma2(pv, wb.y, acc[3]);
                    acc[4] = ffma2(pv, wc.x, acc[4]);
                    acc[5] = ffma2(pv, wc.y, acc[5]);
                    acc[6] = ffma2(pv, wd.x, acc[6]);
                    acc[7] = ffma2(pv, wd.y, acc[7]);
                }
            }
        }
        __syncthreads();
    }
    float raw[16];
    #pragma unroll
    for (int j = 0; j < 8; j++) {
        float2 u = unpack2(acc[j]);
        int oc = ocg*16 + 2*j;
        raw[2*j]   = u.x + cb1[oc];
        raw[2*j+1] = u.y + cb1[oc+1];
    }
    if (act) {
        #pragma unroll
        for (int j = 0; j < 16; j++)
            gRaw1[(b*OC1 + ocg*16 + j)*R1C + od*121 + tid] = raw[j];
    }
    #pragma unroll
    for (int j = 0; j < 16; j++) {
        float s = act ? raw[j] : 0.f;
        float q = s*s;
        #pragma unroll
        for (int off = 16; off; off >>= 1) {
            s += __shfl_down_sync(0xffffffffu, s, off);
            q += __shfl_down_sync(0xffffffffu, q, off);
        }
        if ((tid & 31) == 0) {
            atomicAdd(&gS1c[ocg*16 + j], s);
            atomicAdd(&gQ1c[ocg*16 + j], q);
        }
    }
}

// ================= 7. bg2 partials ==============================================
__global__ void k_bg2(const float* __restrict__ cb1, const float* __restrict__ cg1,
                      const float* __restrict__ cbe1) {
    __shared__ float sc1[OC1];
    int oc = threadIdx.x, cq = blockIdx.x;
    if (oc < OC1) {
        float sc, sh, c1;
        bn1c_params(oc, cb1, cg1, cbe1, sc, sh, c1);
        sc1[oc] = c1;
    }
    __syncthreads();
    float acc[8] = {0,0,0,0,0,0,0,0};
    for (int cc = 0; cc < 8; cc++) {
        int ci = cq*8 + cc;
        float cv = sc1[ci];
        const float* wp = &cwT2[ci*27*OC2 + oc];
        #pragma unroll
        for (int k = 0; k < 27; k++) {
            float v = wp[k*OC2]*cv;
            int kd = k/9, kh = (k/3)%3, kw = k%3;
            #pragma unroll
            for (int pat = 0; pat < 8; pat++) {
                bool fd = pat&4, fh = pat&2, fw = pat&1;
                if (!((fd && kd==0) || (fh && kh==0) || (fw && kw==0)))
                    acc[pat] += v;
            }
        }
    }
    #pragma unroll
    for (int pat = 0; pat < 8; pat++)
        atomicAdd(&gBg2p[pat*OC2 + oc], acc[pat]);
}

// ================= 8. conv2: cp.async pipeline + in-smem BN1 transform ==========
__global__ void k_conv2(const float* __restrict__ cb1, const float* __restrict__ cg1,
                        const float* __restrict__ cbe1) {
    __shared__ int sOff[1859];
    __shared__ float sIn[2][4*1859];
    __shared__ __align__(16) float sW[2][4*216];
    __shared__ float sSc[64], sSh[64], sC1[64];
    int ocg = blockIdx.x, half = blockIdx.y, b = blockIdx.z;
    int tid = threadIdx.x;
    int cBase = half*64;
    if (tid < 64) {
        float sc, sh, c1;
        bn1c_params(cBase + tid, cb1, cg1, cbe1, sc, sh, c1);
        sSc[tid] = sc; sSh[tid] = sh; sC1[tid] = c1;
    }
    for (int i = tid; i < 1859; i += 192) {
        int zz = i/169 - 1, rr = i%169, yy = rr/13 - 1, xx = rr%13 - 1;
        sOff[i] = ((unsigned)zz < 10u && (unsigned)yy < 11u && (unsigned)xx < 11u)
                  ? zz*121 + yy*11 + xx : -1;
    }
    __syncthreads();

    const float* gin = gRaw1 + (size_t)b*OC1*R1C;
    #define C2FILL(S, BUF) {                                                   \
        int c0 = cBase + (S)*4;                                                \
        for (int i = tid; i < 4*1859; i += 192) {                              \
            int cib = i/1859, r = i - cib*1859;                                \
            int off = sOff[r];                                                 \
            cpa4(su32(&sIn[BUF][i]), gin + (c0+cib)*R1C + (off<0?0:off), off>=0); \
        }                                                                      \
        for (int i = tid; i < 4*216; i += 192) {                               \
            int cib = i/216, r = i - cib*216;                                  \
            cpa4(su32(&sW[BUF][cib*216 + r]),                                  \
                 &cwT2[((c0+cib)*27 + (r>>3))*OC2 + ocg*8 + (r&7)], 1);        \
        }                                                                      \
        CP_COMMIT(); }

    C2FILL(0, 0);
    int pos = tid;
    int od = pos/36, oh = (pos%36)/6, ow = pos%6;
    bool act = tid < R2C;
    unsigned long long a0 = 0ull, a1 = 0ull, a2 = 0ull, a3 = 0ull;
    for (int s = 0; s < 16; s++) {
        int buf = s & 1;
        if (s < 15) { C2FILL(s+1, buf^1); CP_WAIT1(); } else { CP_WAIT0(); }
        __syncthreads();
        for (int i = tid; i < 4*1859; i += 192) {
            int cib = i/1859, r = i - cib*1859;
            if (sOff[r] >= 0) {
                int lc = s*4 + cib;
                float rawv = sIn[buf][i];
                sIn[buf][i] = fmaxf(rawv*sSc[lc] + sSh[lc], 0.f) - sC1[lc];
            }
        }
        __syncthreads();
        if (act) {
            #pragma unroll
            for (int cib = 0; cib < 4; cib++) {
                const float* bp = sIn[buf] + cib*1859;
                #pragma unroll
                for (int kd = 0; kd < 3; kd++)
                #pragma unroll
                for (int kh = 0; kh < 3; kh++)
                #pragma unroll
                for (int kw = 0; kw < 3; kw++) {
                    float iv = bp[(2*od + kd)*169 + (2*oh + kh)*13 + 2*ow + kw];
                    unsigned long long pv = pack2(iv);
                    const ulonglong2* wp =
                        (const ulonglong2*)&sW[buf][(cib*27 + kd*9 + kh*3 + kw)*8];
                    ulonglong2 wa = wp[0], wb = wp[1];
                    a0 = ffma2(pv, wa.x, a0);
                    a1 = ffma2(pv, wa.y, a1);
                    a2 = ffma2(pv, wb.x, a2);
                    a3 = ffma2(pv, wb.y, a3);
                }
            }
        }
        __syncthreads();
    }
    if (act) {
        float2 u0 = unpack2(a0), u1 = unpack2(a1);
        float2 u2 = unpack2(a2), u3 = unpack2(a3);
        float vals[8] = {u0.x,u0.y,u1.x,u1.y,u2.x,u2.y,u3.x,u3.y};
        #pragma unroll
        for (int j = 0; j < 8; j++) {
            int oc = ocg*8 + j;
            gP2[half][(b*OC2 + oc)*R2C + pos] = vals[j];
        }
    }
}

// ================= 9. bnd2 ======================================================
__global__ void k_bnd2(const float* __restrict__ cb2, const float* __restrict__ cg2,
                       const float* __restrict__ cbe2) {
    int oc = blockIdx.x, tid = threadIdx.x;
    __shared__ float sBg[8], sX[8], sS, sH;
    if (tid < 8) sBg[tid] = gBg2p[tid*OC2 + oc] + cb2[oc];
    __syncthreads();
    float s = 0.f, q = 0.f;
    for (int i = tid; i < BB*R2C; i += 128) {
        int b = i/R2C, r = i%R2C;
        int od = r/36, oh = (r%36)/6, ow = r%6;
        int pat = ((od==0)<<2) | ((oh==0)<<1) | (ow==0);
        int idx = (b*OC2 + oc)*R2C + r;
        float v = gP2[0][idx] + gP2[1][idx] + sBg[pat];
        s += v; q += v*v;
    }
    __shared__ double ss[128], sq[128];
    ss[tid] = (double)s; sq[tid] = (double)q; __syncthreads();
    for (int st = 64; st; st >>= 1) {
        if (tid < st) { ss[tid] += ss[tid+st]; sq[tid] += sq[tid+st]; }
        __syncthreads();
    }
    if (tid == 0) {
        double S = ss[0], Q = sq[0];
        for (int pat = 0; pat < 8; pat++) {
            int fd = (pat>>2)&1, fh = (pat>>1)&1, fw = pat&1;
            int cd = fd?1:4, ch = fh?1:31, cw = fw?1:31;
            int dh = fh?1:5, dw = fw?1:5;
            double cnt = 2.0*cd*(ch*cw - dh*dw);
            double bg = (double)sBg[pat];
            S += bg*cnt; Q += bg*bg*cnt;
        }
        double N = 10240.0;
        double mu = S/N, var = Q/N - mu*mu;
        double sc = (double)cg2[oc]*rsqrt(var + 1e-5);
        double sh = (double)cbe2[oc] - mu*sc;
        sS = (float)sc; sH = (float)sh;
        for (int pat = 0; pat < 8; pat++) {
            double v = (double)sBg[pat]*sc + sh;
            float x = (float)(v > 0.0 ? v : 0.0);
            sX[pat] = x;
            gX2bg[pat*OC2 + oc] = x;
        }
    }
    __syncthreads();
    float sc = sS, sh = sH;
    for (int i = tid; i < BB*R2C; i += 128) {
        int b = i/R2C, r = i%R2C;
        int od = r/36, oh = (r%36)/6, ow = r%6;
        int pat = ((od==0)<<2) | ((oh==0)<<1) | (ow==0);
        int idx = (b*OC2 + oc)*R2C + r;
        float raw = gP2[0][idx] + gP2[1][idx] + sBg[pat];
        gDelta2[idx] = fmaxf(raw*sc + sh, 0.f) - sX[pat];
    }
}

// ================= 10. nd3 partials =============================================
__global__ void k_nd3() {
    __shared__ float sbg[8*OC2];
    int oc = threadIdx.x, cq = blockIdx.x;
    for (int i = oc; i < 8*OC2; i += 256) sbg[i] = gX2bg[i];
    __syncthreads();
    float acc[12];
    #pragma unroll
    for (int j = 0; j < 12; j++) acc[j] = 0.f;
    for (int cc = 0; cc < 8; cc++) {
        int ci = cq*8 + cc;
        const float* wp = &cwT3[ci*27*OC3 + oc];
        #pragma unroll
        for (int k = 0; k < 27; k++) {
            float w = wp[k*OC3];
            int kd = k/9, kh = (k/3)%3, kw = k%3;
            #pragma unroll
            for (int cs = 0; cs < 12; cs++) {
                int dc = cs>>2, hc = (cs>>1)&1, wc = cs&1;
                bool zpad = (dc==1 && kd==0) || (dc==2 && kd==2);
                bool ypad = hc && kh==0, xpad = wc && kw==0;
                if (!(zpad || ypad || xpad)) {
                    int zb = (dc==1 && kd==1), yb = hc && kh==1, xb = wc && kw==1;
                    acc[cs] += w*sbg[((zb<<2)|(yb<<1)|xb)*OC2 + ci];
                }
            }
        }
    }
    #pragma unroll
    for (int cs = 0; cs < 12; cs++)
        atomicAdd(&gNd3p[cs*OC3 + oc], acc[cs]);
}

// ================= 11. conv3: cp.async pipeline =================================
__global__ void k_conv3() {
    __shared__ int sOff[567];
    __shared__ float sIn[2][4*567];
    __shared__ __align__(16) float sW[2][4*216];
    int ocg = blockIdx.x, qq = blockIdx.y, b = blockIdx.z;
    int tid = threadIdx.x;
    for (int i = tid; i < 567; i += 96) {
        int zz = i/81 - 1, rr = i%81, yy = rr/9 - 1, xx = rr%9 - 1;
        sOff[i] = ((unsigned)zz < 5u && (unsigned)yy < 6u && (unsigned)xx < 6u)
                  ? zz*36 + yy*6 + xx : -1;
    }
    __syncthreads();

    const float* gin = gDelta2 + (size_t)b*OC2*R2C;
    int cBase = qq*64;
    #define C3FILL(S, BUF) {                                                   \
        int c0 = cBase + (S)*4;                                                \
        for (int i = tid; i < 4*567; i += 96) {                                \
            int cib = i/567, r = i - cib*567;                                  \
            int off = sOff[r];                                                 \
            cpa4(su32(&sIn[BUF][i]), gin + (c0+cib)*R2C + (off<0?0:off), off>=0); \
        }                                                                      \
        for (int i = tid; i < 4*216; i += 96) {                                \
            int cib = i/216, r = i - cib*216;                                  \
            cpa4(su32(&sW[BUF][cib*216 + r]),                                  \
                 &cwT3[((c0+cib)*27 + (r>>3))*OC3 + ocg*8 + (r&7)], 1);        \
        }                                                                      \
        CP_COMMIT(); }

    C3FILL(0, 0);
    int sub = tid/48, pos = tid%48;
    int od = pos/16, oh = (pos%16)/4, ow = pos%4;
    unsigned long long a0 = 0ull, a1 = 0ull;
    for (int s = 0; s < 16; s++) {
        int buf = s & 1;
        if (s < 15) { C3FILL(s+1, buf^1); CP_WAIT1(); } else { CP_WAIT0(); }
        __syncthreads();
        #pragma unroll
        for (int cib = 0; cib < 4; cib++) {
            const float* bp = sIn[buf] + cib*567;
            #pragma unroll
            for (int kd = 0; kd < 3; kd++)
            #pragma unroll
            for (int kh = 0; kh < 3; kh++)
            #pragma unroll
            for (int kw = 0; kw < 3; kw++) {
                float iv = bp[(2*od + kd)*81 + (2*oh + kh)*9 + 2*ow + kw];
                unsigned long long pv = pack2(iv);
                const ulonglong2* wp =
                    (const ulonglong2*)&sW[buf][(cib*27 + kd*9 + kh*3 + kw)*8 + sub*4];
                ulonglong2 w = *wp;
                a0 = ffma2(pv, w.x, a0);
                a1 = ffma2(pv, w.y, a1);
            }
        }
        __syncthreads();
    }
    float2 u0 = unpack2(a0), u1 = unpack2(a1);
    float vals[4] = {u0.x, u0.y, u1.x, u1.y};
    #pragma unroll
    for (int j = 0; j < 4; j++) {
        int oc = ocg*8 + sub*4 + j;
        gP3[qq][(b*OC3 + oc)*R3C + pos] = vals[j];
    }
}

// ================= 12. bnout ====================================================
__global__ void k_bnout(const float* __restrict__ cb3, const float* __restrict__ cg3,
                        const float* __restrict__ cbe3, float* __restrict__ out) {
    int oc = blockIdx.x, tid = threadIdx.x;
    __shared__ float snd[12], sS, sH;
    if (tid < 12) snd[tid] = gNd3p[tid*OC3 + oc] + cb3[oc];
    __syncthreads();
    float s = 0.f, q = 0.f;
    if (tid < BB*R3C) {
        int b = tid/R3C, r = tid%R3C;
        int od = r/16, rr = r%16, oh = rr/4, ow = rr%4;
        int dc = (od==0) ? 1 : ((od==2) ? 2 : 0);
        int cs = dc*4 + ((oh==0)<<1) + (ow==0);
        int idx = (b*OC3 + oc)*R3C + r;
        float v = gP3[0][idx] + gP3[1][idx] + gP3[2][idx] + gP3[3][idx] + snd[cs];
        s = v; q = v*v;
    }
    __shared__ double ss[128], sq[128];
    ss[tid] = (double)s; sq[tid] = (double)q; __syncthreads();
    for (int st = 64; st; st >>= 1) {
        if (tid < st) { ss[tid] += ss[tid+st]; sq[tid] += sq[tid+st]; }
        __syncthreads();
    }
    if (tid == 0) {
        double S = ss[0], Q = sq[0];
        for (int cs = 0; cs < 12; cs++) {
            int hc = (cs>>1)&1, wc = cs&1;
            int ch = hc?1:15, cw = wc?1:15, dh = hc?1:3, dw = wc?1:3;
            double cnt = 2.0*(ch*cw - dh*dw);
            double bg = (double)snd[cs];
            S += bg*cnt; Q += bg*bg*cnt;
        }
        double N = 1536.0;
        double mu = S/N, var = Q/N - mu*mu;
        double sc = (double)cg3[oc]*rsqrt(var + 1e-5);
        sS = (float)sc;
        sH = (float)((double)cbe3[oc] - mu*sc);
    }
    __syncthreads();
    float sc = sS, sh = sH;
    for (int i = tid; i < BB*3*256; i += 128) {
        int hw = i % 256, od = (i/256) % 3, b = i/768;
        int oh = hw/16, ow = hw%16;
        float raw;
        int dc = (od==0) ? 1 : ((od==2) ? 2 : 0);
        if (oh < 4 && ow < 4) {
            int r = od*16 + oh*4 + ow;
            int cs = dc*4 + ((oh==0)<<1) + (ow==0);
            int idx = (b*OC3 + oc)*R3C + r;
            raw = gP3[0][idx] + gP3[1][idx] + gP3[2][idx] + gP3[3][idx] + snd[cs];
        } else {
            raw = snd[dc*4 + ((oh==0)<<1) + (ow==0)];
        }
        out[((b*OC3 + oc)*3 + od)*256 + hw] = fmaxf(raw*sc + sh, 0.f);
    }
}

extern "C" void kernel_launch(void* const* d_in, const int* in_sizes, int n_in,
                              void* d_out, int out_size) {
    int base = (n_in >= 25) ? 5 : 2;
    const float* vf   = (const float*)d_in[0];
    const int*  coords= (const int*)d_in[1];
    const float* w1 = (const float*)d_in[base+0];
    const float* b1 = (const float*)d_in[base+1];
    const float* g1 = (const float*)d_in[base+2];
    const float* be1= (const float*)d_in[base+3];
    const float* w2 = (const float*)d_in[base+4];
    const float* b2 = (const float*)d_in[base+5];
    const float* g2 = (const float*)d_in[base+6];
    const float* be2= (const float*)d_in[base+7];
    const float* cw1= (const float*)d_in[base+8];
    const float* cb1= (const float*)d_in[base+9];
    const float* cg1= (const float*)d_in[base+10];
    const float* cbe1=(const float*)d_in[base+11];
    const float* cw2= (const float*)d_in[base+12];
    const float* cb2= (const float*)d_in[base+13];
    const float* cg2= (const float*)d_in[base+14];
    const float* cbe2=(const float*)d_in[base+15];
    const float* cw3= (const float*)d_in[base+16];
    const float* cb3= (const float*)d_in[base+17];
    const float* cg3= (const float*)d_in[base+18];
    const float* cbe3=(const float*)d_in[base+19];
    float* out = (float*)d_out;

    static cudaStream_t s1 = nullptr;
    static cudaEvent_t eInit, eT;
    if (!s1) {
        cudaStreamCreateWithFlags(&s1, cudaStreamNonBlocking);
        cudaEventCreateWithFlags(&eInit, cudaEventDisableTiming);
        cudaEventCreateWithFlags(&eT, cudaEventDisableTiming);
    }

    k_init<<<80, 256>>>();
    cudaEventRecord(eInit, 0);
    cudaStreamWaitEvent(s1, eInit, 0);
    k_setupT<<<3024, 256, 0, s1>>>(cw1, cw2, cw3);
    cudaEventRecord(eT, s1);
    k_pass1<<<BB*NV/16, 256>>>(vf, coords, w1, b1);
    k_vfe2<<<BB*NV/VPB, 128>>>(w2, b2, g1, be1);
    k_scatter<<<dim3(GC/32, BB), 256>>>(g2, be2);
    cudaStreamWaitEvent(0, eT, 0);
    k_conv1<<<dim3(8, 10, BB), 128>>>(cb1);
    k_bg2<<<16, 256>>>(cb1, cg1, cbe1);
    k_conv2<<<dim3(32, 2, BB), 192>>>(cb1, cg1, cbe1);
    k_bnd2<<<OC2, 128>>>(cb2, cg2, cbe2);
    k_nd3<<<32, 256>>>();
    k_conv3<<<dim3(32, 4, BB), 96>>>();
    k_bnout<<<OC3, 128>>>(cb3, cg3, cbe3, out);
}

// round 17
// speedup vs baseline: 1.3843x; 1.3843x over previous
#include <cuda_runtime.h>

#define BB 2
#define NV 12000
#define NP 32
#define CIN 5
#define CV1 64
#define CV2 128
#define GD 20
#define GC 8000
#define OC1 128
#define R1C 1210      // (10,11,11)
#define OC2 256
#define R2C 180       // (5,6,6)
#define OC3 256
#define R3C 48        // (3,4,4)

__device__ double dS1y[CV1], dQ1y[CV1];
__device__ float  fS2[CV2], fQ2[CV2];
__device__ float  gF1[BB*NV*CV1];
__device__ float  gY2[BB*NV*CV2];
__device__ int    gWin[BB*GC];
__device__ float  gSub[BB*CV2*GC];
__device__ float  gRaw1[BB*OC1*R1C];
__device__ float  gS1c[OC1], gQ1c[OC1];
__device__ float  gDelta1P[BB*OC1*1320];   // [b][ci][110 rows][12] (pad col 11 = 0)
__device__ float  gBg2p[8*OC2];
__device__ float  gP2[2][BB*OC2*R2C];
__device__ float  gX2bg[8*OC2];
__device__ float  gDelta2P[BB*OC2*240];    // [b][ci][5 z][6 y][8] (pads 6,7 = 0)
__device__ float  gNd3p[12*OC3];
__device__ float  gP3[4][BB*OC3*R3C];
__device__ float  cwT1[CV2*27*OC1];
__device__ float  cwT2[OC1*27*OC2];
__device__ float  cwT3[OC2*27*OC3];

// ---- packed f32x2 helpers ----
__device__ __forceinline__ unsigned long long pack2(float v) {
    unsigned long long p;
    asm("mov.b64 %0, {%1, %1};" : "=l"(p) : "r"(__float_as_uint(v)));
    return p;
}
__device__ __forceinline__ unsigned long long ffma2(unsigned long long a,
                                                    unsigned long long b,
                                                    unsigned long long c) {
    unsigned long long d;
    asm("fma.rn.f32x2 %0, %1, %2, %3;" : "=l"(d) : "l"(a), "l"(b), "l"(c));
    return d;
}
__device__ __forceinline__ float2 unpack2(unsigned long long p) {
    unsigned lo, hi;
    asm("mov.b64 {%0, %1}, %2;" : "=r"(lo), "=r"(hi) : "l"(p));
    float2 r; r.x = __uint_as_float(lo); r.y = __uint_as_float(hi);
    return r;
}

// ---- cp.async helpers ----
__device__ __forceinline__ unsigned su32(const void* p) {
    return (unsigned)__cvta_generic_to_shared(p);
}
__device__ __forceinline__ void cpa4(unsigned sa, const float* g, int ok) {
    asm volatile("cp.async.ca.shared.global [%0], [%1], 4, %2;"
                 :: "r"(sa), "l"(g), "r"(ok ? 4 : 0));
}
__device__ __forceinline__ void cpa16(unsigned sa, const float* g) {
    asm volatile("cp.async.cg.shared.global [%0], [%1], 16;"
                 :: "r"(sa), "l"(g));
}
#define CP_COMMIT() asm volatile("cp.async.commit_group;" ::: "memory")
#define CP_WAIT1()  asm volatile("cp.async.wait_group 1;" ::: "memory")
#define CP_WAIT0()  asm volatile("cp.async.wait_group 0;" ::: "memory")

// BN1c params from conv1's atomic stats
__device__ __forceinline__ void bn1c_params(int c, const float* cb1,
                                            const float* cg1, const float* cbe1,
                                            float& sc, float& sh, float& c1) {
    float S = gS1c[c], Q = gQ1c[c];
    float bg = cb1[c];
    const float N = 81920.f, bgn = N - (float)(BB*R1C);
    float mu = (S + bg*bgn)/N;
    float var = (Q + bg*bg*bgn)/N - mu*mu;
    sc = cg1[c]*rsqrtf(var + 1e-5f);
    sh = cbe1[c] - mu*sc;
    c1 = fmaxf(bg*sc + sh, 0.f);
}

// ================= 1. init =======================================================
__global__ void k_init() {
    int i = blockIdx.x*256 + threadIdx.x;
    if (i < BB*GC) gWin[i] = -1;
    if (i < CV1) { dS1y[i] = 0.0; dQ1y[i] = 0.0; }
    if (i < CV2) { fS2[i] = 0.f; fQ2[i] = 0.f; }
    if (i < OC1) { gS1c[i] = 0.f; gQ1c[i] = 0.f; }
    if (i < 8*OC2)  gBg2p[i] = 0.f;
    if (i < 12*OC3) gNd3p[i] = 0.f;
}

// ================= 2. setupT (side stream) ======================================
__global__ void k_setupT(const float* __restrict__ cw1, const float* __restrict__ cw2,
                         const float* __restrict__ cw3) {
    int b = blockIdx.x;
    const float* src; float* dst; int J, OC;
    if (b < 432)       { src = cw1; dst = cwT1; J = 3456; OC = 128; }
    else if (b < 1296) { b -= 432;  src = cw2; dst = cwT2; J = 3456; OC = 256; }
    else               { b -= 1296; src = cw3; dst = cwT3; J = 6912; OC = 256; }
    int tO = OC/32;
    int to = b % tO, tj = b / tO;
    __shared__ float sm[32][33];
    int tx = threadIdx.x % 32, ty = threadIdx.x / 32;
    int j0 = tj*32, o0 = to*32;
    #pragma unroll
    for (int r = 0; r < 4; r++)
        sm[ty + r*8][tx] = src[(o0 + ty + r*8)*J + j0 + tx];
    __syncthreads();
    #pragma unroll
    for (int r = 0; r < 4; r++)
        dst[(j0 + ty + r*8)*OC + o0 + tx] = sm[tx][ty + r*8];
}

// ================= 3. pass1: cp.async (16B) double-buffered =====================
__global__ void k_pass1(const float* __restrict__ vf, const int* __restrict__ coords,
                        const float* __restrict__ w1, const float* __restrict__ b1) {
    __shared__ float sw[CV1*CIN], sb[CV1];
    __shared__ __align__(16) float sx[2][4*NP*CIN];
    __shared__ float rs[256], rq[256];
    int tid = threadIdx.x;
    int vbase = blockIdx.x*16;
    for (int i = tid; i < CV1*CIN; i += 256) sw[i] = w1[i];
    if (tid < CV1) sb[tid] = b1[tid];
    if (tid < 16) {
        int v = vbase + tid;
        int d = coords[v*3], h = coords[v*3+1], w = coords[v*3+2];
        if ((unsigned)d < GD && (unsigned)h < GD && (unsigned)w < GD)
            atomicMax(&gWin[(v/NV)*GC + (d*GD + h)*GD + w], v % NV);
    }
    for (int i = tid; i < 160; i += 256)
        cpa16(su32(&sx[0][i*4]), vf + (size_t)vbase*160 + i*4);
    CP_COMMIT();
    __syncthreads();
    int vloc = tid >> 6, oc = tid & 63;
    float w[CIN];
    #pragma unroll
    for (int c = 0; c < CIN; c++) w[c] = sw[oc*CIN + c];
    float bb = sb[oc];
    float sAcc = 0.f, qAcc = 0.f;
    for (int g = 0; g < 4; g++) {
        int buf = g & 1;
        if (g < 3) {
            int v1 = vbase + (g+1)*4;
            for (int i = tid; i < 160; i += 256)
                cpa16(su32(&sx[buf^1][i*4]), vf + (size_t)v1*160 + i*4);
            CP_COMMIT();
            CP_WAIT1();
        } else {
            CP_WAIT0();
        }
        __syncthreads();
        const float* xp = sx[buf] + vloc*NP*CIN;
        float m = -1e30f;
        #pragma unroll 4
        for (int p = 0; p < NP; p++) {
            float y = bb;
            #pragma unroll
            for (int c = 0; c < CIN; c++) y += w[c]*xp[p*CIN + c];
            m = fmaxf(m, y);
            sAcc += y; qAcc += y*y;
        }
        gF1[(vbase + g*4 + vloc)*CV1 + oc] = m;
        __syncthreads();
    }
    rs[tid] = sAcc; rq[tid] = qAcc;
    __syncthreads();
    if (tid < 64) {
        float st = rs[tid] + rs[tid+64] + rs[tid+128] + rs[tid+192];
        float qt = rq[tid] + rq[tid+64] + rq[tid+128] + rq[tid+192];
        atomicAdd(&dS1y[tid], (double)st);
        atomicAdd(&dQ1y[tid], (double)qt);
    }
}

// ================= 4. vfe2 ======================================================
#define VPB 96
__global__ void k_vfe2(const float* __restrict__ w2, const float* __restrict__ b2,
                       const float* __restrict__ g1, const float* __restrict__ be1) {
    __shared__ float sf[CV1*34];
    __shared__ float sw2s[CV1*129];
    __shared__ float sc1s[CV1], sh1s[CV1];
    int tid = threadIdx.x;
    int vb0 = blockIdx.x*VPB;
    if (tid < CV1) {
        double N = (double)BB*NV*NP;
        double mu = dS1y[tid]/N, var = dQ1y[tid]/N - mu*mu;
        double sc = (double)g1[tid]*rsqrt(var + 1e-5);
        sc1s[tid] = (float)sc;
        sh1s[tid] = (float)((double)be1[tid] - mu*sc);
    }
    for (int i = tid; i < CV2*CV1; i += 128)
        cpa4(su32(&sw2s[(i & 63)*129 + (i >> 6)]), w2 + i, 1);
    for (int i = tid; i < 32*CV1; i += 128)
        cpa4(su32(&sf[(i & 63)*34 + (i >> 6)]), &gF1[(size_t)(vb0 + (i >> 6))*CV1 + (i & 63)], 1);
    CP_COMMIT();
    float bb2 = b2[tid];
    float s = 0.f, q = 0.f;
    for (int g = 0; g < 3; g++) {
        int vb = vb0 + g*32;
        CP_WAIT0();
        __syncthreads();
        for (int i = tid; i < 32*CV1; i += 128) {
            int c = i & 63, v = i >> 6;
            float f = sf[c*34 + v];
            sf[c*34 + v] = fmaxf(f*sc1s[c] + sh1s[c], 0.f);
        }
        __syncthreads();
        unsigned long long acc[16] = {};
        #pragma unroll 4
        for (int c = 0; c < CV1; c++) {
            unsigned long long w2p = pack2(sw2s[c*129 + tid]);
            const unsigned long long* fp = (const unsigned long long*)&sf[c*34];
            #pragma unroll
            for (int p = 0; p < 16; p++)
                acc[p] = ffma2(w2p, fp[p], acc[p]);
        }
        #pragma unroll
        for (int p = 0; p < 16; p++) {
            float2 y = unpack2(acc[p]);
            y.x += bb2; y.y += bb2;
            gY2[(size_t)(vb + 2*p    )*CV2 + tid] = y.x;
            gY2[(size_t)(vb + 2*p + 1)*CV2 + tid] = y.y;
            s += y.x + y.y; q += y.x*y.x + y.y*y.y;
        }
        __syncthreads();
        if (g < 2) {
            int vn = vb0 + (g+1)*32;
            for (int i = tid; i < 32*CV1; i += 128)
                cpa4(su32(&sf[(i & 63)*34 + (i >> 6)]),
                     &gF1[(size_t)(vn + (i >> 6))*CV1 + (i & 63)], 1);
            CP_COMMIT();
        }
    }
    atomicAdd(&fS2[tid], s); atomicAdd(&fQ2[tid], q);
}

// ================= 5. scatter ===================================================
__global__ void k_scatter(const float* __restrict__ g2, const float* __restrict__ be2) {
    __shared__ int swin[32];
    __shared__ float st[CV2*33];
    int tid = threadIdx.x;
    int c0 = blockIdx.x*32, b = blockIdx.y;
    if (tid < 32) swin[tid] = gWin[b*GC + c0 + tid];
    int ch = tid & 127;
    double N = (double)BB*NV;
    double mu = (double)fS2[ch]/N, var = (double)fQ2[ch]/N - mu*mu;
    double scd = (double)g2[ch]*rsqrt(var + 1e-5);
    float sc = (float)scd;
    float sh = (float)((double)be2[ch] - mu*scd);
    __syncthreads();
    #pragma unroll
    for (int pp = 0; pp < 16; pp++) {
        int cl = pp*2 + (tid >> 7);
        int win = swin[cl];
        float v = 0.f;
        if (win >= 0) v = fmaxf(gY2[(size_t)(b*NV + win)*CV2 + ch]*sc + sh, 0.f);
        st[ch*33 + cl] = v;
    }
    __syncthreads();
    #pragma unroll
    for (int k = 0; k < 16; k++) {
        int i = tid + k*256;
        int oc = i >> 5, cl = i & 31;
        gSub[(b*CV2 + oc)*GC + c0 + cl] = st[oc*33 + cl];
    }
}

// ================= 6. conv1: float4 cp.async pipeline, 16 oc ====================
// sIn rows: [cib][kd 0..2][yy' 0..22][28]; payload x=0..19 at offsets 4..23
// (23 rows per kd: input y = -1..21 -> yy' = 0..22; rows 0,21,22 stay zero)
__global__ void k_conv1(const float* __restrict__ cb1) {
    __shared__ __align__(16) float sIn[2][4*1932];     // 4 * (3*23*28)
    __shared__ __align__(16) float sW[2][4*432];
    int ocg = blockIdx.x, od = blockIdx.y, b = blockIdx.z;   // ocg 0..7
    int tid = threadIdx.x;
    for (int i = tid; i < 2*4*1932; i += 128) ((float*)sIn)[i] = 0.f;
    __syncthreads();

    const float* gin = gSub + (size_t)b*CV2*GC;
    #define C1FILL(S, BUF) {                                                   \
        int c0 = (S)*4;                                                        \
        for (int i = tid; i < 240; i += 128) {                                 \
            int cib = i/60, rr = i - cib*60, kd = rr/20, yy = rr - kd*20;      \
            int z = 2*od - 1 + kd;                                             \
            if ((unsigned)z < 20u) {                                           \
                const float* src = gin + (size_t)(c0+cib)*GC + (z*20 + yy)*20; \
                unsigned dst = su32(&sIn[BUF][((cib*3 + kd)*23 + yy + 1)*28 + 4]); \
                cpa16(dst, src); cpa16(dst+16, src+4); cpa16(dst+32, src+8);   \
                cpa16(dst+48, src+12); cpa16(dst+64, src+16);                  \
            }                                                                  \
        }                                                                      \
        for (int i = tid; i < 432; i += 128) {                                 \
            int cib = i/108, r = i - cib*108, k = r >> 2, v2 = r & 3;          \
            cpa16(su32(&sW[BUF][cib*432 + k*16 + v2*4]),                       \
                  &cwT1[((c0+cib)*27 + k)*OC1 + ocg*16 + v2*4]);               \
        }                                                                      \
        CP_COMMIT(); }

    C1FILL(0, 0);
    int oh = tid/11, ow = tid%11;
    bool act = tid < 121;
    unsigned long long acc[8] = {};
    for (int s = 0; s < 32; s++) {
        int buf = s & 1;
        if (s < 31) { C1FILL(s+1, buf^1); CP_WAIT1(); } else { CP_WAIT0(); }
        __syncthreads();
        if (act) {
            #pragma unroll
            for (int cib = 0; cib < 4; cib++) {
                const float* bp = sIn[buf] + cib*1932;
                #pragma unroll
                for (int kd = 0; kd < 3; kd++)
                #pragma unroll
                for (int kh = 0; kh < 3; kh++)
                #pragma unroll
                for (int kw = 0; kw < 3; kw++) {
                    float iv = bp[(kd*23 + 2*oh + kh)*28 + 3 + 2*ow + kw];
                    unsigned long long pv = pack2(iv);
                    const ulonglong2* wp =
                        (const ulonglong2*)&sW[buf][(cib*27 + kd*9 + kh*3 + kw)*16];
                    ulonglong2 wa = wp[0], wb = wp[1], wc = wp[2], wd = wp[3];
                    acc[0] = ffma2(pv, wa.x, acc[0]);
                    acc[1] = ffma2(pv, wa.y, acc[1]);
                    acc[2] = ffma2(pv, wb.x, acc[2]);
                    acc[3] = ffma2(pv, wb.y, acc[3]);
                    acc[4] = ffma2(pv, wc.x, acc[4]);
                    acc[5] = ffma2(pv, wc.y, acc[5]);
                    acc[6] = ffma2(pv, wd.x, acc[6]);
                    acc[7] = ffma2(pv, wd.y, acc[7]);
                }
            }
        }
        __syncthreads();
    }
    float raw[16];
    #pragma unroll
    for (int j = 0; j < 8; j++) {
        float2 u = unpack2(acc[j]);
        int oc = ocg*16 + 2*j;
        raw[2*j]   = u.x + cb1[oc];
        raw[2*j+1] = u.y + cb1[oc+1];
    }
    if (act) {
        #pragma unroll
        for (int j = 0; j < 16; j++)
            gRaw1[(b*OC1 + ocg*16 + j)*R1C + od*121 + tid] = raw[j];
    }
    #pragma unroll
    for (int j = 0; j < 16; j++) {
        float s = act ? raw[j] : 0.f;
        float q = s*s;
        #pragma unroll
        for (int off = 16; off; off >>= 1) {
            s += __shfl_down_sync(0xffffffffu, s, off);
            q += __shfl_down_sync(0xffffffffu, q, off);
        }
        if ((tid & 31) == 0) {
            atomicAdd(&gS1c[ocg*16 + j], s);
            atomicAdd(&gQ1c[ocg*16 + j], q);
        }
    }
}

// ================= 7. delta1: BN1-transform to padded layout ====================
__global__ void k_delta1(const float* __restrict__ cb1, const float* __restrict__ cg1,
                         const float* __restrict__ cbe1) {
    int bo = blockIdx.x;                    // 256 blocks = (b,oc)
    int b = bo >> 7, oc = bo & 127;
    __shared__ float pS, pH, pC;
    if (threadIdx.x == 0) {
        float sc, sh, c1;
        bn1c_params(oc, cb1, cg1, cbe1, sc, sh, c1);
        pS = sc; pH = sh; pC = c1;
    }
    __syncthreads();
    float sc = pS, sh = pH, c1 = pC;
    const float* src = gRaw1 + (size_t)(b*OC1 + oc)*R1C;
    float* dst = gDelta1P + (size_t)(b*OC1 + oc)*1320;
    for (int i = threadIdx.x; i < 1320; i += 128) {
        int row = i/12, x = i - row*12;
        float v = 0.f;
        if (x < 11) v = fmaxf(src[row*11 + x]*sc + sh, 0.f) - c1;
        dst[i] = v;
    }
}

// ================= 8. bg2 partials ==============================================
__global__ void k_bg2(const float* __restrict__ cb1, const float* __restrict__ cg1,
                      const float* __restrict__ cbe1) {
    __shared__ float sc1[OC1];
    int oc = threadIdx.x, cq = blockIdx.x;
    if (oc < OC1) {
        float sc, sh, c1;
        bn1c_params(oc, cb1, cg1, cbe1, sc, sh, c1);
        sc1[oc] = c1;
    }
    __syncthreads();
    float acc[8] = {0,0,0,0,0,0,0,0};
    for (int cc = 0; cc < 8; cc++) {
        int ci = cq*8 + cc;
        float cv = sc1[ci];
        const float* wp = &cwT2[ci*27*OC2 + oc];
        #pragma unroll
        for (int k = 0; k < 27; k++) {
            float v = wp[k*OC2]*cv;
            int kd = k/9, kh = (k/3)%3, kw = k%3;
            #pragma unroll
            for (int pat = 0; pat < 8; pat++) {
                bool fd = pat&4, fh = pat&2, fw = pat&1;
                if (!((fd && kd==0) || (fh && kh==0) || (fw && kw==0)))
                    acc[pat] += v;
            }
        }
    }
    #pragma unroll
    for (int pat = 0; pat < 8; pat++)
        atomicAdd(&gBg2p[pat*OC2 + oc], acc[pat]);
}

// ================= 9. conv2: float4 cp.async pipeline (no transform) ============
// sIn rows: [cib][zz' 0..10][yy' 0..12][16]; payload x=0..11 at offsets 4..15
__global__ void k_conv2() {
    __shared__ __align__(16) float sIn[2][4*2288];
    __shared__ __align__(16) float sW[2][4*216];
    int ocg = blockIdx.x, half = blockIdx.y, b = blockIdx.z;
    int tid = threadIdx.x;
    for (int i = tid; i < 2*4*2288; i += 192) ((float*)sIn)[i] = 0.f;
    __syncthreads();
    int cBase = half*64;

    #define C2FILL(S, BUF) {                                                   \
        int c0 = cBase + (S)*4;                                                \
        for (int i = tid; i < 440; i += 192) {                                 \
            int cib = i/110, rr = i - cib*110, zz = rr/11, yy = rr - zz*11;    \
            const float* src = gDelta1P +                                      \
                ((size_t)(b*OC1 + c0 + cib)*110 + zz*11 + yy)*12;              \
            unsigned dst = su32(&sIn[BUF][((cib*11 + zz + 1)*13 + yy + 1)*16 + 4]); \
            cpa16(dst, src); cpa16(dst+16, src+4); cpa16(dst+32, src+8);       \
        }                                                                      \
        for (int i = tid; i < 216; i += 192) {                                 \
            int cib = i/54, r = i - cib*54, k = r >> 1, v2 = r & 1;            \
            cpa16(su32(&sW[BUF][cib*216 + k*8 + v2*4]),                        \
                  &cwT2[((c0+cib)*27 + k)*OC2 + ocg*8 + v2*4]);                \
        }                                                                      \
        CP_COMMIT(); }

    C2FILL(0, 0);
    int pos = tid;
    int od = pos/36, oh = (pos%36)/6, ow = pos%6;
    bool act = tid < R2C;
    unsigned long long a0 = 0ull, a1 = 0ull, a2 = 0ull, a3 = 0ull;
    for (int s = 0; s < 16; s++) {
        int buf = s & 1;
        if (s < 15) { C2FILL(s+1, buf^1); CP_WAIT1(); } else { CP_WAIT0(); }
        __syncthreads();
        if (act) {
            #pragma unroll
            for (int cib = 0; cib < 4; cib++) {
                const float* bp = sIn[buf] + cib*2288;
                #pragma unroll
                for (int kd = 0; kd < 3; kd++)
                #pragma unroll
                for (int kh = 0; kh < 3; kh++)
                #pragma unroll
                for (int kw = 0; kw < 3; kw++) {
                    float iv = bp[((2*od + kd)*13 + 2*oh + kh)*16 + 3 + 2*ow + kw];
                    unsigned long long pv = pack2(iv);
                    const ulonglong2* wp =
                        (const ulonglong2*)&sW[buf][(cib*27 + kd*9 + kh*3 + kw)*8];
                    ulonglong2 wa = wp[0], wb = wp[1];
                    a0 = ffma2(pv, wa.x, a0);
                    a1 = ffma2(pv, wa.y, a1);
                    a2 = ffma2(pv, wb.x, a2);
                    a3 = ffma2(pv, wb.y, a3);
                }
            }
        }
        __syncthreads();
    }
    if (act) {
        float2 u0 = unpack2(a0), u1 = unpack2(a1);
        float2 u2 = unpack2(a2), u3 = unpack2(a3);
        float vals[8] = {u0.x,u0.y,u1.x,u1.y,u2.x,u2.y,u3.x,u3.y};
        #pragma unroll
        for (int j = 0; j < 8; j++) {
            int oc = ocg*8 + j;
            gP2[half][(b*OC2 + oc)*R2C + pos] = vals[j];
        }
    }
}

// ================= 10. bnd2: stats + padded delta2 ==============================
__global__ void k_bnd2(const float* __restrict__ cb2, const float* __restrict__ cg2,
                       const float* __restrict__ cbe2) {
    int oc = blockIdx.x, tid = threadIdx.x;
    __shared__ float sBg[8], sX[8], sS, sH;
    if (tid < 8) sBg[tid] = gBg2p[tid*OC2 + oc] + cb2[oc];
    __syncthreads();
    float s = 0.f, q = 0.f;
    for (int i = tid; i < BB*R2C; i += 128) {
        int b = i/R2C, r = i%R2C;
        int od = r/36, oh = (r%36)/6, ow = r%6;
        int pat = ((od==0)<<2) | ((oh==0)<<1) | (ow==0);
        int idx = (b*OC2 + oc)*R2C + r;
        float v = gP2[0][idx] + gP2[1][idx] + sBg[pat];
        s += v; q += v*v;
    }
    __shared__ double ss[128], sq[128];
    ss[tid] = (double)s; sq[tid] = (double)q; __syncthreads();
    for (int st = 64; st; st >>= 1) {
        if (tid < st) { ss[tid] += ss[tid+st]; sq[tid] += sq[tid+st]; }
        __syncthreads();
    }
    if (tid == 0) {
        double S = ss[0], Q = sq[0];
        for (int pat = 0; pat < 8; pat++) {
            int fd = (pat>>2)&1, fh = (pat>>1)&1, fw = pat&1;
            int cd = fd?1:4, ch = fh?1:31, cw = fw?1:31;
            int dh = fh?1:5, dw = fw?1:5;
            double cnt = 2.0*cd*(ch*cw - dh*dw);
            double bg = (double)sBg[pat];
            S += bg*cnt; Q += bg*bg*cnt;
        }
        double N = 10240.0;
        double mu = S/N, var = Q/N - mu*mu;
        double sc = (double)cg2[oc]*rsqrt(var + 1e-5);
        double sh = (double)cbe2[oc] - mu*sc;
        sS = (float)sc; sH = (float)sh;
        for (int pat = 0; pat < 8; pat++) {
            double v = (double)sBg[pat]*sc + sh;
            float x = (float)(v > 0.0 ? v : 0.0);
            sX[pat] = x;
            gX2bg[pat*OC2 + oc] = x;
        }
    }
    __syncthreads();
    float sc = sS, sh = sH;
    for (int i = tid; i < BB*240; i += 128) {
        int b = i/240, rr = i - b*240, od = rr/48, hw = rr - od*48, oh = hw/8, ow = hw & 7;
        float v = 0.f;
        if (ow < 6) {
            int r = od*36 + oh*6 + ow;
            int pat = ((od==0)<<2) | ((oh==0)<<1) | (ow==0);
            int idx = (b*OC2 + oc)*R2C + r;
            float raw = gP2[0][idx] + gP2[1][idx] + sBg[pat];
            v = fmaxf(raw*sc + sh, 0.f) - sX[pat];
        }
        gDelta2P[(size_t)(b*OC2 + oc)*240 + od*48 + oh*8 + ow] = v;
    }
}

// ================= 11. nd3 partials =============================================
__global__ void k_nd3() {
    __shared__ float sbg[8*OC2];
    int oc = threadIdx.x, cq = blockIdx.x;
    for (int i = oc; i < 8*OC2; i += 256) sbg[i] = gX2bg[i];
    __syncthreads();
    float acc[12];
    #pragma unroll
    for (int j = 0; j < 12; j++) acc[j] = 0.f;
    for (int cc = 0; cc < 8; cc++) {
        int ci = cq*8 + cc;
        const float* wp = &cwT3[ci*27*OC3 + oc];
        #pragma unroll
        for (int k = 0; k < 27; k++) {
            float w = wp[k*OC3];
            int kd = k/9, kh = (k/3)%3, kw = k%3;
            #pragma unroll
            for (int cs = 0; cs < 12; cs++) {
                int dc = cs>>2, hc = (cs>>1)&1, wc = cs&1;
                bool zpad = (dc==1 && kd==0) || (dc==2 && kd==2);
                bool ypad = hc && kh==0, xpad = wc && kw==0;
                if (!(zpad || ypad || xpad)) {
                    int zb = (dc==1 && kd==1), yb = hc && kh==1, xb = wc && kw==1;
                    acc[cs] += w*sbg[((zb<<2)|(yb<<1)|xb)*OC2 + ci];
                }
            }
        }
    }
    #pragma unroll
    for (int cs = 0; cs < 12; cs++)
        atomicAdd(&gNd3p[cs*OC3 + oc], acc[cs]);
}

// ================= 12. conv3: float4 cp.async pipeline ==========================
// sIn rows: [cib][zz' 0..6][yy' 0..8][12]; payload x=0..7 at offsets 4..11
__global__ void k_conv3() {
    __shared__ __align__(16) float sIn[2][4*756];
    __shared__ __align__(16) float sW[2][4*216];
    int ocg = blockIdx.x, qq = blockIdx.y, b = blockIdx.z;
    int tid = threadIdx.x;
    for (int i = tid; i < 2*4*756; i += 96) ((float*)sIn)[i] = 0.f;
    __syncthreads();
    int cBase = qq*64;

    #define C3FILL(S, BUF) {                                                   \
        int c0 = cBase + (S)*4;                                                \
        for (int i = tid; i < 120; i += 96) {                                  \
            int cib = i/30, rr = i - cib*30, zz = rr/6, yy = rr - zz*6;        \
            const float* src = gDelta2P +                                      \
                (size_t)(b*OC2 + c0 + cib)*240 + zz*48 + yy*8;                 \
            unsigned dst = su32(&sIn[BUF][((cib*7 + zz + 1)*9 + yy + 1)*12 + 4]); \
            cpa16(dst, src); cpa16(dst+16, src+4);                             \
        }                                                                      \
        for (int i = tid; i < 216; i += 96) {                                  \
            int cib = i/54, r = i - cib*54, k = r >> 1, v2 = r & 1;            \
            cpa16(su32(&sW[BUF][cib*216 + k*8 + v2*4]),                        \
                  &cwT3[((c0+cib)*27 + k)*OC3 + ocg*8 + v2*4]);                \
        }                                                                      \
        CP_COMMIT(); }

    C3FILL(0, 0);
    int sub = tid/48, pos = tid%48;
    int od = pos/16, oh = (pos%16)/4, ow = pos%4;
    unsigned long long a0 = 0ull, a1 = 0ull;
    for (int s = 0; s < 16; s++) {
        int buf = s & 1;
        if (s < 15) { C3FILL(s+1, buf^1); CP_WAIT1(); } else { CP_WAIT0(); }
        __syncthreads();
        #pragma unroll
        for (int cib = 0; cib < 4; cib++) {
            const float* bp = sIn[buf] + cib*756;
            #pragma unroll
            for (int kd = 0; kd < 3; kd++)
            #pragma unroll
            for (int kh = 0; kh < 3; kh++)
            #pragma unroll
            for (int kw = 0; kw < 3; kw++) {
                float iv = bp[((2*od + kd)*9 + 2*oh + kh)*12 + 3 + 2*ow + kw];
                unsigned long long pv = pack2(iv);
                const ulonglong2* wp =
                    (const ulonglong2*)&sW[buf][(cib*27 + kd*9 + kh*3 + kw)*8 + sub*4];
                ulonglong2 w = *wp;
                a0 = ffma2(pv, w.x, a0);
                a1 = ffma2(pv, w.y, a1);
            }
        }
        __syncthreads();
    }
    float2 u0 = unpack2(a0), u1 = unpack2(a1);
    float vals[4] = {u0.x, u0.y, u1.x, u1.y};
    #pragma unroll
    for (int j = 0; j < 4; j++) {
        int oc = ocg*8 + sub*4 + j;
        gP3[qq][(b*OC3 + oc)*R3C + pos] = vals[j];
    }
}

// ================= 13. bnout ====================================================
__global__ void k_bnout(const float* __restrict__ cb3, const float* __restrict__ cg3,
                        const float* __restrict__ cbe3, float* __restrict__ out) {
    int oc = blockIdx.x, tid = threadIdx.x;
    __shared__ float snd[12], sS, sH;
    if (tid < 12) snd[tid] = gNd3p[tid*OC3 + oc] + cb3[oc];
    __syncthreads();
    float s = 0.f, q = 0.f;
    if (tid < BB*R3C) {
        int b = tid/R3C, r = tid%R3C;
        int od = r/16, rr = r%16, oh = rr/4, ow = rr%4;
        int dc = (od==0) ? 1 : ((od==2) ? 2 : 0);
        int cs = dc*4 + ((oh==0)<<1) + (ow==0);
        int idx = (b*OC3 + oc)*R3C + r;
        float v = gP3[0][idx] + gP3[1][idx] + gP3[2][idx] + gP3[3][idx] + snd[cs];
        s = v; q = v*v;
    }
    __shared__ double ss[128], sq[128];
    ss[tid] = (double)s; sq[tid] = (double)q; __syncthreads();
    for (int st = 64; st; st >>= 1) {
        if (tid < st) { ss[tid] += ss[tid+st]; sq[tid] += sq[tid+st]; }
        __syncthreads();
    }
    if (tid == 0) {
        double S = ss[0], Q = sq[0];
        for (int cs = 0; cs < 12; cs++) {
            int hc = (cs>>1)&1, wc = cs&1;
            int ch = hc?1:15, cw = wc?1:15, dh = hc?1:3, dw = wc?1:3;
            double cnt = 2.0*(ch*cw - dh*dw);
            double bg = (double)snd[cs];
            S += bg*cnt; Q += bg*bg*cnt;
        }
        double N = 1536.0;
        double mu = S/N, var = Q/N - mu*mu;
        double sc = (double)cg3[oc]*rsqrt(var + 1e-5);
        sS = (float)sc;
        sH = (float)((double)cbe3[oc] - mu*sc);
    }
    __syncthreads();
    float sc = sS, sh = sH;
    for (int i = tid; i < BB*3*256; i += 128) {
        int hw = i % 256, od = (i/256) % 3, b = i/768;
        int oh = hw/16, ow = hw%16;
        float raw;
        int dc = (od==0) ? 1 : ((od==2) ? 2 : 0);
        if (oh < 4 && ow < 4) {
            int r = od*16 + oh*4 + ow;
            int cs = dc*4 + ((oh==0)<<1) + (ow==0);
            int idx = (b*OC3 + oc)*R3C + r;
            raw = gP3[0][idx] + gP3[1][idx] + gP3[2][idx] + gP3[3][idx] + snd[cs];
        } else {
            raw = snd[dc*4 + ((oh==0)<<1) + (ow==0)];
        }
        out[((b*OC3 + oc)*3 + od)*256 + hw] = fmaxf(raw*sc + sh, 0.f);
    }
}

extern "C" void kernel_launch(void* const* d_in, const int* in_sizes, int n_in,
                              void* d_out, int out_size) {
    int base = (n_in >= 25) ? 5 : 2;
    const float* vf   = (const float*)d_in[0];
    const int*  coords= (const int*)d_in[1];
    const float* w1 = (const float*)d_in[base+0];
    const float* b1 = (const float*)d_in[base+1];
    const float* g1 = (const float*)d_in[base+2];
    const float* be1= (const float*)d_in[base+3];
    const float* w2 = (const float*)d_in[base+4];
    const float* b2 = (const float*)d_in[base+5];
    const float* g2 = (const float*)d_in[base+6];
    const float* be2= (const float*)d_in[base+7];
    const float* cw1= (const float*)d_in[base+8];
    const float* cb1= (const float*)d_in[base+9];
    const float* cg1= (const float*)d_in[base+10];
    const float* cbe1=(const float*)d_in[base+11];
    const float* cw2= (const float*)d_in[base+12];
    const float* cb2= (const float*)d_in[base+13];
    const float* cg2= (const float*)d_in[base+14];
    const float* cbe2=(const float*)d_in[base+15];
    const float* cw3= (const float*)d_in[base+16];
    const float* cb3= (const float*)d_in[base+17];
    const float* cg3= (const float*)d_in[base+18];
    const float* cbe3=(const float*)d_in[base+19];
    float* out = (float*)d_out;

    static cudaStream_t s1 = nullptr;
    static cudaEvent_t eInit, eT;
    if (!s1) {
        cudaStreamCreateWithFlags(&s1, cudaStreamNonBlocking);
        cudaEventCreateWithFlags(&eInit, cudaEventDisableTiming);
        cudaEventCreateWithFlags(&eT, cudaEventDisableTiming);
    }

    k_init<<<80, 256>>>();
    cudaEventRecord(eInit, 0);
    cudaStreamWaitEvent(s1, eInit, 0);
    k_setupT<<<3024, 256, 0, s1>>>(cw1, cw2, cw3);
    cudaEventRecord(eT, s1);
    k_pass1<<<BB*NV/16, 256>>>(vf, coords, w1, b1);
    k_vfe2<<<BB*NV/VPB, 128>>>(w2, b2, g1, be1);
    k_scatter<<<dim3(GC/32, BB), 256>>>(g2, be2);
    cudaStreamWaitEvent(0, eT, 0);
    k_conv1<<<dim3(8, 10, BB), 128>>>(cb1);
    k_delta1<<<BB*OC1, 128>>>(cb1, cg1, cbe1);
    k_bg2<<<16, 256>>>(cb1, cg1, cbe1);
    k_conv2<<<dim3(32, 2, BB), 192>>>();
    k_bnd2<<<OC2, 128>>>(cb2, cg2, cbe2);
    k_nd3<<<32, 256>>>();
    k_conv3<<<dim3(32, 4, BB), 96>>>();
    k_bnout<<<OC3, 128>>>(cb3, cg3, cbe3, out);
}